// round 4
// baseline (speedup 1.0000x reference)
#include <cuda_runtime.h>
#include <cuda_bf16.h>

// Bicubic x4 upsample, Keys a=-0.5, matching jax.image.resize(method="cubic").
//   input (16,3,256,256) f32 -> output (16,3,1024,1024) f32
// Block = 256 threads, 32x32 input cells -> 128x128 output tile.
//   Phase B: horizontal 4-phase pass straight from gmem -> smem sh[36][32] float4
//   Phase C: vertical 4-phase pass with rolling 5-tap register window, float4 stores
// Borders (blocks on image edge only) use masked+renormalized weights (jax semantics).

#define IN_W   256
#define IN_H   256
#define OUT_W  1024
#define PLANE_IN  (IN_W * IN_H)
#define PLANE_OUT (OUT_W * OUT_W)

// Keys(a=-0.5) phase weights on tap offsets -2..+2 (exact binary fractions).
#define A0 (-0.0439453125f)
#define A1 ( 0.3896484375f)
#define A2 ( 0.7275390625f)
#define A3 (-0.0732421875f)
#define B0 (-0.0068359375f)
#define B1 ( 0.0908203125f)
#define B2 ( 0.9638671875f)
#define B3 (-0.0478515625f)

// Masked + renormalized 5-tap dot for one phase at border cell q (scalar).
__device__ __forceinline__ float border_dot5(int q, const float wt[5],
                                             float v0, float v1, float v2,
                                             float v3, float v4)
{
    float w[5]; float s = 0.f;
#pragma unroll
    for (int j = 0; j < 5; j++) {
        int idx = q - 2 + j;
        float ww = (idx >= 0 && idx < IN_W) ? wt[j] : 0.f;
        w[j] = ww; s += ww;
    }
    float inv = 1.0f / s;
    float r = w[0] * v0;
    r = fmaf(w[1], v1, r);
    r = fmaf(w[2], v2, r);
    r = fmaf(w[3], v3, r);
    r = fmaf(w[4], v4, r);
    return r * inv;
}

// Masked + renormalized 5-tap vertical phase on float4 lanes.
__device__ __forceinline__ float4 border_dot5_v4(int q, const float wt[5],
                                                 float4 v0, float4 v1, float4 v2,
                                                 float4 v3, float4 v4)
{
    float w[5]; float s = 0.f;
#pragma unroll
    for (int j = 0; j < 5; j++) {
        int idx = q - 2 + j;
        float ww = (idx >= 0 && idx < IN_H) ? wt[j] : 0.f;
        w[j] = ww; s += ww;
    }
    float inv = 1.0f / s;
    float4 o;
    o.x = (fmaf(w[4], v4.x, fmaf(w[3], v3.x, fmaf(w[2], v2.x, fmaf(w[1], v1.x, w[0] * v0.x))))) * inv;
    o.y = (fmaf(w[4], v4.y, fmaf(w[3], v3.y, fmaf(w[2], v2.y, fmaf(w[1], v1.y, w[0] * v0.y))))) * inv;
    o.z = (fmaf(w[4], v4.z, fmaf(w[3], v3.z, fmaf(w[2], v2.z, fmaf(w[1], v1.z, w[0] * v0.z))))) * inv;
    o.w = (fmaf(w[4], v4.w, fmaf(w[3], v3.w, fmaf(w[2], v2.w, fmaf(w[1], v1.w, w[0] * v0.w))))) * inv;
    return o;
}

__global__ void __launch_bounds__(256, 5)
bicubic4x_sep2_kernel(const float* __restrict__ in, float* __restrict__ out)
{
    __shared__ float4 sh[36][32];      // horizontally filtered halo rows (18 KB)

    const int tid   = threadIdx.x;
    const int qx0   = blockIdx.x * 32;
    const int qy0   = blockIdx.y * 32;
    const int plane = blockIdx.z;

    const bool xedge = (blockIdx.x == 0) | (blockIdx.x == 7);
    const bool yedge = (blockIdx.y == 0) | (blockIdx.y == 7);

    const float* ip = in + (size_t)plane * PLANE_IN;

    static const float TA[5]  = {A0,  A1,  A2,  A3,  0.f};
    static const float TB[5]  = {B0,  B1,  B2,  B3,  0.f};
    static const float TBr[5] = {0.f, B3,  B2,  B1,  B0 };
    static const float TAr[5] = {0.f, A3,  A2,  A1,  A0 };

    // ---------- Phase B: horizontal pass, direct from gmem ----------
    {
        const int q  = tid & 31;          // cell within tile row
        const int r0 = tid >> 5;          // 0..7
        const int qg = qx0 + q;           // global cell x
#pragma unroll
        for (int i = 0; i < 5; i++) {
            int r = r0 + i * 8;
            if (r < 36) {
                int gy = qy0 - 2 + r;
                gy = gy < 0 ? 0 : (gy > IN_H - 1 ? IN_H - 1 : gy);
                const float* row = ip + gy * IN_W;

                float v0, v1, v2, v3, v4;
                if (!xedge) {
                    const float* p = row + qg - 2;
                    v0 = __ldg(p + 0); v1 = __ldg(p + 1); v2 = __ldg(p + 2);
                    v3 = __ldg(p + 3); v4 = __ldg(p + 4);
                } else {
                    int c0 = qg - 2, c1 = qg - 1, c2 = qg, c3 = qg + 1, c4 = qg + 2;
                    c0 = c0 < 0 ? 0 : c0;  c1 = c1 < 0 ? 0 : c1;
                    c3 = c3 > IN_W - 1 ? IN_W - 1 : c3;
                    c4 = c4 > IN_W - 1 ? IN_W - 1 : c4;
                    v0 = __ldg(row + c0); v1 = __ldg(row + c1); v2 = __ldg(row + c2);
                    v3 = __ldg(row + c3); v4 = __ldg(row + c4);
                }

                float4 h;
                if (!xedge || (qg >= 2 && qg <= IN_W - 3)) {
                    h.x = fmaf(A0, v0, fmaf(A1, v1, fmaf(A2, v2, A3 * v3)));
                    h.y = fmaf(B0, v0, fmaf(B1, v1, fmaf(B2, v2, B3 * v3)));
                    h.z = fmaf(B3, v1, fmaf(B2, v2, fmaf(B1, v3, B0 * v4)));
                    h.w = fmaf(A3, v1, fmaf(A2, v2, fmaf(A1, v3, A0 * v4)));
                } else {
                    h.x = border_dot5(qg, TA,  v0, v1, v2, v3, v4);
                    h.y = border_dot5(qg, TB,  v0, v1, v2, v3, v4);
                    h.z = border_dot5(qg, TBr, v0, v1, v2, v3, v4);
                    h.w = border_dot5(qg, TAr, v0, v1, v2, v3, v4);
                }
                sh[r][q] = h;
            }
        }
    }
    __syncthreads();

    // ---------- Phase C: vertical pass, rolling 5-tap register window ----------
    {
        const int cx = tid & 31;          // float4 output column
        const int rg = tid >> 5;          // 0..7, handles input rows rg*4 .. rg*4+3
        const int rbase = rg * 4;

        float* opc = out + (size_t)plane * PLANE_OUT
                         + (size_t)(qx0 * 4) + (size_t)cx * 4;

        float4 v0 = sh[rbase + 0][cx];
        float4 v1 = sh[rbase + 1][cx];
        float4 v2 = sh[rbase + 2][cx];
        float4 v3 = sh[rbase + 3][cx];
        float4 v4 = sh[rbase + 4][cx];

#pragma unroll
        for (int c = 0; c < 4; c++) {
            const int qyg = qy0 + rbase + c;
            float* op = opc + (size_t)(qyg * 4) * OUT_W;

            if (!yedge || (qyg >= 2 && qyg <= IN_H - 3)) {
                float4 o;
                o.x = fmaf(A0, v0.x, fmaf(A1, v1.x, fmaf(A2, v2.x, A3 * v3.x)));
                o.y = fmaf(A0, v0.y, fmaf(A1, v1.y, fmaf(A2, v2.y, A3 * v3.y)));
                o.z = fmaf(A0, v0.z, fmaf(A1, v1.z, fmaf(A2, v2.z, A3 * v3.z)));
                o.w = fmaf(A0, v0.w, fmaf(A1, v1.w, fmaf(A2, v2.w, A3 * v3.w)));
                *reinterpret_cast<float4*>(op) = o;

                o.x = fmaf(B0, v0.x, fmaf(B1, v1.x, fmaf(B2, v2.x, B3 * v3.x)));
                o.y = fmaf(B0, v0.y, fmaf(B1, v1.y, fmaf(B2, v2.y, B3 * v3.y)));
                o.z = fmaf(B0, v0.z, fmaf(B1, v1.z, fmaf(B2, v2.z, B3 * v3.z)));
                o.w = fmaf(B0, v0.w, fmaf(B1, v1.w, fmaf(B2, v2.w, B3 * v3.w)));
                *reinterpret_cast<float4*>(op + OUT_W) = o;

                o.x = fmaf(B3, v1.x, fmaf(B2, v2.x, fmaf(B1, v3.x, B0 * v4.x)));
                o.y = fmaf(B3, v1.y, fmaf(B2, v2.y, fmaf(B1, v3.y, B0 * v4.y)));
                o.z = fmaf(B3, v1.z, fmaf(B2, v2.z, fmaf(B1, v3.z, B0 * v4.z)));
                o.w = fmaf(B3, v1.w, fmaf(B2, v2.w, fmaf(B1, v3.w, B0 * v4.w)));
                *reinterpret_cast<float4*>(op + 2 * OUT_W) = o;

                o.x = fmaf(A3, v1.x, fmaf(A2, v2.x, fmaf(A1, v3.x, A0 * v4.x)));
                o.y = fmaf(A3, v1.y, fmaf(A2, v2.y, fmaf(A1, v3.y, A0 * v4.y)));
                o.z = fmaf(A3, v1.z, fmaf(A2, v2.z, fmaf(A1, v3.z, A0 * v4.z)));
                o.w = fmaf(A3, v1.w, fmaf(A2, v2.w, fmaf(A1, v3.w, A0 * v4.w)));
                *reinterpret_cast<float4*>(op + 3 * OUT_W) = o;
            } else {
                *reinterpret_cast<float4*>(op)             = border_dot5_v4(qyg, TA,  v0, v1, v2, v3, v4);
                *reinterpret_cast<float4*>(op + OUT_W)     = border_dot5_v4(qyg, TB,  v0, v1, v2, v3, v4);
                *reinterpret_cast<float4*>(op + 2 * OUT_W) = border_dot5_v4(qyg, TBr, v0, v1, v2, v3, v4);
                *reinterpret_cast<float4*>(op + 3 * OUT_W) = border_dot5_v4(qyg, TAr, v0, v1, v2, v3, v4);
            }

            if (c < 3) {                   // roll the window: 1 new LDS.128
                v0 = v1; v1 = v2; v2 = v3; v3 = v4;
                v4 = sh[rbase + c + 5][cx];
            }
        }
    }
}

extern "C" void kernel_launch(void* const* d_in, const int* in_sizes, int n_in,
                              void* d_out, int out_size)
{
    const float* x   = (const float*)d_in[0];
    float*       out = (float*)d_out;

    dim3 grid(8, 8, 48);   // 8x8 tiles per plane, 48 planes
    bicubic4x_sep2_kernel<<<grid, 256>>>(x, out);
}

// round 5
// speedup vs baseline: 1.1382x; 1.1382x over previous
#include <cuda_runtime.h>
#include <cuda_bf16.h>

// Bicubic x4 upsample, Keys a=-0.5, matching jax.image.resize(method="cubic").
//   input (16,3,256,256) f32 -> output (16,3,1024,1024) f32
// Block = 256 threads, 32x32 input cells -> 128x128 output tile.
//   Phase A: stage 36x36 input halo in smem (coalesced gmem loads)
//   Phase B: horizontal 4-phase pass from smem -> sh[36][32] float4
//   Phase C: vertical 4-phase pass, rolling 5-tap register window, float4 stores
// Borders (edge blocks only) use masked+renormalized weights (jax semantics).

#define IN_W   256
#define IN_H   256
#define OUT_W  1024
#define PLANE_IN  (IN_W * IN_H)
#define PLANE_OUT (OUT_W * OUT_W)

// Keys(a=-0.5) phase weights on tap offsets -2..+2 (exact binary fractions).
#define A0 (-0.0439453125f)
#define A1 ( 0.3896484375f)
#define A2 ( 0.7275390625f)
#define A3 (-0.0732421875f)
#define B0 (-0.0068359375f)
#define B1 ( 0.0908203125f)
#define B2 ( 0.9638671875f)
#define B3 (-0.0478515625f)

// Masked + renormalized 5-tap dot for one phase at border cell q (scalar).
__device__ __forceinline__ float border_dot5(int q, const float wt[5],
                                             float v0, float v1, float v2,
                                             float v3, float v4)
{
    float w[5]; float s = 0.f;
#pragma unroll
    for (int j = 0; j < 5; j++) {
        int idx = q - 2 + j;
        float ww = (idx >= 0 && idx < IN_W) ? wt[j] : 0.f;
        w[j] = ww; s += ww;
    }
    float inv = 1.0f / s;
    float r = w[0] * v0;
    r = fmaf(w[1], v1, r);
    r = fmaf(w[2], v2, r);
    r = fmaf(w[3], v3, r);
    r = fmaf(w[4], v4, r);
    return r * inv;
}

// Masked + renormalized 5-tap vertical phase on float4 lanes.
__device__ __forceinline__ float4 border_dot5_v4(int q, const float wt[5],
                                                 float4 v0, float4 v1, float4 v2,
                                                 float4 v3, float4 v4)
{
    float w[5]; float s = 0.f;
#pragma unroll
    for (int j = 0; j < 5; j++) {
        int idx = q - 2 + j;
        float ww = (idx >= 0 && idx < IN_H) ? wt[j] : 0.f;
        w[j] = ww; s += ww;
    }
    float inv = 1.0f / s;
    float4 o;
    o.x = (fmaf(w[4], v4.x, fmaf(w[3], v3.x, fmaf(w[2], v2.x, fmaf(w[1], v1.x, w[0] * v0.x))))) * inv;
    o.y = (fmaf(w[4], v4.y, fmaf(w[3], v3.y, fmaf(w[2], v2.y, fmaf(w[1], v1.y, w[0] * v0.y))))) * inv;
    o.z = (fmaf(w[4], v4.z, fmaf(w[3], v3.z, fmaf(w[2], v2.z, fmaf(w[1], v1.z, w[0] * v0.z))))) * inv;
    o.w = (fmaf(w[4], v4.w, fmaf(w[3], v3.w, fmaf(w[2], v2.w, fmaf(w[1], v1.w, w[0] * v0.w))))) * inv;
    return o;
}

__global__ void __launch_bounds__(256, 5)
bicubic4x_sep3_kernel(const float* __restrict__ in, float* __restrict__ out)
{
    __shared__ float  sin_t[36][40];   // input halo (5.76 KB, padded row)
    __shared__ float4 sh[36][32];      // horizontally filtered rows (18 KB)

    const int tid   = threadIdx.x;
    const int qx0   = blockIdx.x * 32;
    const int qy0   = blockIdx.y * 32;
    const int plane = blockIdx.z;

    const bool xedge = (blockIdx.x == 0) | (blockIdx.x == 7);
    const bool yedge = (blockIdx.y == 0) | (blockIdx.y == 7);

    const float* ip = in + (size_t)plane * PLANE_IN;

    static const float TA[5]  = {A0,  A1,  A2,  A3,  0.f};
    static const float TB[5]  = {B0,  B1,  B2,  B3,  0.f};
    static const float TBr[5] = {0.f, B3,  B2,  B1,  B0 };
    static const float TAr[5] = {0.f, A3,  A2,  A1,  A0 };

    // ---------- Phase A: stage 36x36 halo (coalesced, clamped) ----------
#pragma unroll
    for (int i = tid; i < 36 * 36; i += 256) {
        int r = i / 36;
        int c = i - r * 36;
        int gy = qy0 - 2 + r;  gy = gy < 0 ? 0 : (gy > IN_H - 1 ? IN_H - 1 : gy);
        int gx = qx0 - 2 + c;  gx = gx < 0 ? 0 : (gx > IN_W - 1 ? IN_W - 1 : gx);
        sin_t[r][c] = __ldg(ip + gy * IN_W + gx);
    }
    __syncthreads();

    // ---------- Phase B: horizontal pass (36 rows x 32 cells) ----------
#pragma unroll
    for (int t = tid; t < 36 * 32; t += 256) {
        int r = t >> 5;           // halo row 0..35
        int q = t & 31;           // local cell 0..31
        int qg = qx0 + q;         // global cell x

        float v0 = sin_t[r][q + 0];
        float v1 = sin_t[r][q + 1];
        float v2 = sin_t[r][q + 2];
        float v3 = sin_t[r][q + 3];
        float v4 = sin_t[r][q + 4];

        float4 h;
        if (!xedge || (qg >= 2 && qg <= IN_W - 3)) {
            h.x = fmaf(A0, v0, fmaf(A1, v1, fmaf(A2, v2, A3 * v3)));
            h.y = fmaf(B0, v0, fmaf(B1, v1, fmaf(B2, v2, B3 * v3)));
            h.z = fmaf(B3, v1, fmaf(B2, v2, fmaf(B1, v3, B0 * v4)));
            h.w = fmaf(A3, v1, fmaf(A2, v2, fmaf(A1, v3, A0 * v4)));
        } else {
            h.x = border_dot5(qg, TA,  v0, v1, v2, v3, v4);
            h.y = border_dot5(qg, TB,  v0, v1, v2, v3, v4);
            h.z = border_dot5(qg, TBr, v0, v1, v2, v3, v4);
            h.w = border_dot5(qg, TAr, v0, v1, v2, v3, v4);
        }
        sh[r][q] = h;
    }
    __syncthreads();

    // ---------- Phase C: vertical pass, rolling 5-tap register window ----------
    {
        const int cx = tid & 31;          // float4 output column
        const int rg = tid >> 5;          // 0..7, input rows rg*4 .. rg*4+3
        const int rbase = rg * 4;

        float* opc = out + (size_t)plane * PLANE_OUT
                         + (size_t)(qx0 * 4) + (size_t)cx * 4;

        float4 v0 = sh[rbase + 0][cx];
        float4 v1 = sh[rbase + 1][cx];
        float4 v2 = sh[rbase + 2][cx];
        float4 v3 = sh[rbase + 3][cx];
        float4 v4 = sh[rbase + 4][cx];

#pragma unroll
        for (int c = 0; c < 4; c++) {
            const int qyg = qy0 + rbase + c;
            float* op = opc + (size_t)(qyg * 4) * OUT_W;

            if (!yedge || (qyg >= 2 && qyg <= IN_H - 3)) {
                float4 o;
                o.x = fmaf(A0, v0.x, fmaf(A1, v1.x, fmaf(A2, v2.x, A3 * v3.x)));
                o.y = fmaf(A0, v0.y, fmaf(A1, v1.y, fmaf(A2, v2.y, A3 * v3.y)));
                o.z = fmaf(A0, v0.z, fmaf(A1, v1.z, fmaf(A2, v2.z, A3 * v3.z)));
                o.w = fmaf(A0, v0.w, fmaf(A1, v1.w, fmaf(A2, v2.w, A3 * v3.w)));
                *reinterpret_cast<float4*>(op) = o;

                o.x = fmaf(B0, v0.x, fmaf(B1, v1.x, fmaf(B2, v2.x, B3 * v3.x)));
                o.y = fmaf(B0, v0.y, fmaf(B1, v1.y, fmaf(B2, v2.y, B3 * v3.y)));
                o.z = fmaf(B0, v0.z, fmaf(B1, v1.z, fmaf(B2, v2.z, B3 * v3.z)));
                o.w = fmaf(B0, v0.w, fmaf(B1, v1.w, fmaf(B2, v2.w, B3 * v3.w)));
                *reinterpret_cast<float4*>(op + OUT_W) = o;

                o.x = fmaf(B3, v1.x, fmaf(B2, v2.x, fmaf(B1, v3.x, B0 * v4.x)));
                o.y = fmaf(B3, v1.y, fmaf(B2, v2.y, fmaf(B1, v3.y, B0 * v4.y)));
                o.z = fmaf(B3, v1.z, fmaf(B2, v2.z, fmaf(B1, v3.z, B0 * v4.z)));
                o.w = fmaf(B3, v1.w, fmaf(B2, v2.w, fmaf(B1, v3.w, B0 * v4.w)));
                *reinterpret_cast<float4*>(op + 2 * OUT_W) = o;

                o.x = fmaf(A3, v1.x, fmaf(A2, v2.x, fmaf(A1, v3.x, A0 * v4.x)));
                o.y = fmaf(A3, v1.y, fmaf(A2, v2.y, fmaf(A1, v3.y, A0 * v4.y)));
                o.z = fmaf(A3, v1.z, fmaf(A2, v2.z, fmaf(A1, v3.z, A0 * v4.z)));
                o.w = fmaf(A3, v1.w, fmaf(A2, v2.w, fmaf(A1, v3.w, A0 * v4.w)));
                *reinterpret_cast<float4*>(op + 3 * OUT_W) = o;
            } else {
                *reinterpret_cast<float4*>(op)             = border_dot5_v4(qyg, TA,  v0, v1, v2, v3, v4);
                *reinterpret_cast<float4*>(op + OUT_W)     = border_dot5_v4(qyg, TB,  v0, v1, v2, v3, v4);
                *reinterpret_cast<float4*>(op + 2 * OUT_W) = border_dot5_v4(qyg, TBr, v0, v1, v2, v3, v4);
                *reinterpret_cast<float4*>(op + 3 * OUT_W) = border_dot5_v4(qyg, TAr, v0, v1, v2, v3, v4);
            }

            if (c < 3) {                   // roll window: one new LDS.128
                v0 = v1; v1 = v2; v2 = v3; v3 = v4;
                v4 = sh[rbase + c + 5][cx];
            }
        }
    }
}

extern "C" void kernel_launch(void* const* d_in, const int* in_sizes, int n_in,
                              void* d_out, int out_size)
{
    const float* x   = (const float*)d_in[0];
    float*       out = (float*)d_out;

    dim3 grid(8, 8, 48);   // 8x8 tiles per plane, 48 planes
    bicubic4x_sep3_kernel<<<grid, 256>>>(x, out);
}